// round 11
// baseline (speedup 1.0000x reference)
#include <cuda_runtime.h>
#include <cuda_bf16.h>
#include <cstdint>

// Problem constants
constexpr int B  = 8;
constexpr int S  = 4096;
constexpr int D  = 64;
constexpr int DS = 16;
constexpr int CH = 64;                       // chunk length (tokens)
constexpr int NCHUNKS = B * S / CH;          // 512
constexpr int NTOK = B * S;                  // 32768

constexpr int SXT = 68;                      // sxT row stride (floats)
constexpr int SHT = 66;                      // shT row stride (floats)

// Scratch
__device__ float g_A  [NTOK * DS * DS];      // 33.5 MB per-token A matrices
__device__ float g_Bx [NTOK * DS];           //  2  MB per-token Bx
__device__ float g_Pref[NTOK * DS * DS];     // 33.5 MB per-token prefix transitions
__device__ float g_r  [NTOK * DS];           //  2  MB per-token prefix offsets
__device__ float g_H0 [NCHUNKS * DS];        // state at each chunk start

// ---------------------------------------------------------------------------
// packed f32x2 helpers
// ---------------------------------------------------------------------------
using u64 = unsigned long long;

__device__ __forceinline__ u64 pack2(float lo, float hi) {
    u64 r; asm("mov.b64 %0, {%1, %2};" : "=l"(r) : "f"(lo), "f"(hi)); return r;
}
__device__ __forceinline__ void unpack2(u64 v, float& lo, float& hi) {
    asm("mov.b64 {%0, %1}, %2;" : "=f"(lo), "=f"(hi) : "l"(v));
}
__device__ __forceinline__ u64 fma2(u64 a, u64 b, u64 c) {
    u64 d; asm("fma.rn.f32x2 %0, %1, %2, %3;" : "=l"(d) : "l"(a), "l"(b), "l"(c)); return d;
}
__device__ __forceinline__ u64 mul2(u64 a, u64 b) {
    u64 d; asm("mul.rn.f32x2 %0, %1, %2;" : "=l"(d) : "l"(a), "l"(b)); return d;
}
__device__ __forceinline__ u64 add2(u64 a, u64 b) {
    u64 d; asm("add.rn.f32x2 %0, %1, %2;" : "=l"(d) : "l"(a), "l"(b)); return d;
}

// transpose-load a 64x64 token-major x chunk into sxT[k*SXT + t]
__device__ __forceinline__ void load_xT(const float* __restrict__ xc, float* sxT, int tid) {
    for (int e = tid; e < 2048; e += 256) {
        const int k  = e & 63;
        const int tp = e >> 6;                 // token pair 0..31
        const float a = xc[(2 * tp)     * 64 + k];
        const float b = xc[(2 * tp + 1) * 64 + k];
        *(float2*)&sxT[k * SXT + 2 * tp] = make_float2(a, b);
    }
}

// ---------------------------------------------------------------------------
// KA: A = x @ W_A + b_A  ->  g_A.   High occupancy (4 CTAs/SM).
// ---------------------------------------------------------------------------
__global__ __launch_bounds__(256, 4)
void kA(const float* __restrict__ x,
        const float* __restrict__ WA, const float* __restrict__ bA)
{
    __shared__ float sxT[64 * SXT];
    const int c   = blockIdx.x;
    const int tid = threadIdx.x;
    const float* xc = x + (size_t)c * CH * D;

    load_xT(xc, sxT, tid);
    __syncthreads();

    const int i = tid;                       // output column 0..255
    const float bias = bA[i];
    float* gA = g_A + (size_t)c * CH * 256;

    for (int half = 0; half < 2; ++half) {
        u64 acc[16];
        #pragma unroll
        for (int p = 0; p < 16; ++p) acc[p] = pack2(bias, bias);
        float w0 = WA[0 * 256 + i];
        float w1 = WA[1 * 256 + i];
        #pragma unroll 4
        for (int k = 0; k < 64; ++k) {
            const float w2 = (k < 62) ? WA[(k + 2) * 256 + i] : 0.0f;
            const u64 wp = pack2(w0, w0);
            const float* xrow = &sxT[k * SXT + half * 32];
            #pragma unroll
            for (int q = 0; q < 8; ++q) {
                const ulonglong2 xv = *(const ulonglong2*)&xrow[q * 4];
                acc[2 * q]     = fma2(xv.x, wp, acc[2 * q]);
                acc[2 * q + 1] = fma2(xv.y, wp, acc[2 * q + 1]);
            }
            w0 = w1; w1 = w2;
        }
        #pragma unroll
        for (int p = 0; p < 16; ++p) {
            float lo, hi; unpack2(acc[p], lo, hi);
            const int t0 = half * 32 + 2 * p;
            gA[t0 * 256 + i]       = lo;
            gA[(t0 + 1) * 256 + i] = hi;
        }
    }
}

// ---------------------------------------------------------------------------
// KB: Bx[t,n] = sum_d (x@W_B + b_B)[t,n,d] * x[t,d]  ->  g_Bx.  3 CTAs/SM.
// ---------------------------------------------------------------------------
__global__ __launch_bounds__(256, 3)
void kB(const float* __restrict__ x,
        const float* __restrict__ WB, const float* __restrict__ bB)
{
    __shared__ float sxT[64 * SXT];
    const int c   = blockIdx.x;
    const int tid = threadIdx.x;
    const float* xc = x + (size_t)c * CH * D;

    load_xT(xc, sxT, tid);
    __syncthreads();

    const int n  = tid >> 4;
    const int dq = tid & 15;
    const float4 bb = *(const float4*)&bB[n * 64 + dq * 4];
    const float bbc[4] = {bb.x, bb.y, bb.z, bb.w};
    const float4* WB4 = (const float4*)WB;
    const int widx = n * 16 + dq;
    float* gBx = g_Bx + (size_t)c * CH * 16;

    for (int tt = 0; tt < 8; ++tt) {
        const int base = tt * 8;
        u64 acc[4][4];
        #pragma unroll
        for (int p = 0; p < 4; ++p)
            #pragma unroll
            for (int cc = 0; cc < 4; ++cc) acc[p][cc] = pack2(bbc[cc], bbc[cc]);

        for (int kg = 0; kg < 16; ++kg) {
            float4 w[4];
            #pragma unroll
            for (int j = 0; j < 4; ++j) w[j] = WB4[(kg * 4 + j) * 256 + widx];
            #pragma unroll
            for (int j = 0; j < 4; ++j) {
                const int k = kg * 4 + j;
                const u64 wpx = pack2(w[j].x, w[j].x);
                const u64 wpy = pack2(w[j].y, w[j].y);
                const u64 wpz = pack2(w[j].z, w[j].z);
                const u64 wpw = pack2(w[j].w, w[j].w);
                const ulonglong2 xa = *(const ulonglong2*)&sxT[k * SXT + base];
                const ulonglong2 xb = *(const ulonglong2*)&sxT[k * SXT + base + 4];
                const u64 xp[4] = {xa.x, xa.y, xb.x, xb.y};
                #pragma unroll
                for (int p = 0; p < 4; ++p) {
                    acc[p][0] = fma2(xp[p], wpx, acc[p][0]);
                    acc[p][1] = fma2(xp[p], wpy, acc[p][1]);
                    acc[p][2] = fma2(xp[p], wpz, acc[p][2]);
                    acc[p][3] = fma2(xp[p], wpw, acc[p][3]);
                }
            }
        }
        // epilogue: dot with x over this thread's 4 d's, reduce across dq
        #pragma unroll
        for (int p = 0; p < 4; ++p) {
            const int t0 = base + 2 * p;
            u64 xd0 = *(const u64*)&sxT[(dq * 4 + 0) * SXT + t0];
            u64 v = mul2(acc[p][0], xd0);
            #pragma unroll
            for (int cc = 1; cc < 4; ++cc) {
                const u64 xdc = *(const u64*)&sxT[(dq * 4 + cc) * SXT + t0];
                v = fma2(acc[p][cc], xdc, v);
            }
            v = add2(v, __shfl_xor_sync(0xffffffffu, v, 8, 16));
            v = add2(v, __shfl_xor_sync(0xffffffffu, v, 4, 16));
            v = add2(v, __shfl_xor_sync(0xffffffffu, v, 2, 16));
            v = add2(v, __shfl_xor_sync(0xffffffffu, v, 1, 16));
            if (dq == 0) {
                float lo, hi; unpack2(v, lo, hi);
                gBx[t0 * 16 + n]       = lo;
                gBx[(t0 + 1) * 16 + n] = hi;
            }
        }
    }
}

// ---------------------------------------------------------------------------
// KS: per chunk — serial scan over 64 steps, emitting every prefix.
// smem: sA[64*256] sBx[64*16] sP[2*256] sq[2*16] = 71808 B  -> 3 CTAs/SM
// ---------------------------------------------------------------------------
__global__ __launch_bounds__(256, 3)
void kS(void)
{
    extern __shared__ float sm[];
    float* sA  = sm;                  // 64*256
    float* sBx = sA  + 64 * 256;      // 64*16
    float* sP  = sBx + 64 * 16;       // 2*256
    float* sq  = sP  + 512;           // 2*16

    const int c   = blockIdx.x;
    const int tid = threadIdx.x;

    // load A chunk (coalesced float4) + Bx chunk
    {
        const float4* src = (const float4*)(g_A + (size_t)c * CH * 256);
        float4* dst = (float4*)sA;
        for (int i = tid; i < (CH * 256) / 4; i += 256) dst[i] = src[i];
        for (int i = tid; i < CH * 16; i += 256) sBx[i] = g_Bx[(size_t)c * CH * 16 + i];
    }

    const int pi = tid >> 4, pj = tid & 15;
    sP[tid] = (pi == pj) ? 1.0f : 0.0f;
    if (tid < 16) sq[tid] = 0.0f;
    __syncthreads();

    float* gP = g_Pref + (size_t)c * CH * 256;
    float* gr = g_r    + (size_t)c * CH * 16;
    int cur = 0;
    for (int t = 0; t < CH; ++t) {
        const float* At = &sA[t * 256];
        float np0 = 0.0f, np1 = 0.0f;
        #pragma unroll
        for (int k = 0; k < 16; k += 2) {
            np0 += At[pi * 16 + k]     * sP[cur * 256 + k * 16 + pj];
            np1 += At[pi * 16 + k + 1] * sP[cur * 256 + (k + 1) * 16 + pj];
        }
        const float np = np0 + np1;
        float nq = 0.0f;
        if (tid < 16) {
            nq = sBx[t * 16 + tid];
            #pragma unroll
            for (int k = 0; k < 16; ++k)
                nq += At[tid * 16 + k] * sq[cur * 16 + k];
        }
        sP[(cur ^ 1) * 256 + tid] = np;
        if (tid < 16) sq[(cur ^ 1) * 16 + tid] = nq;
        gP[t * 256 + tid] = np;                    // fire-and-forget STG
        if (tid < 16) gr[t * 16 + tid] = nq;
        cur ^= 1;
        __syncthreads();
    }
}

// ---------------------------------------------------------------------------
// K2: per batch — serial scan over 64 chunk-final (P,q) pairs -> g_H0
// ---------------------------------------------------------------------------
__global__ __launch_bounds__(256)
void k2_chain(void)
{
    extern __shared__ float sm[];
    float* cP = sm;            // 64*256
    float* cq = cP + 64 * 256; // 64*16

    const int b   = blockIdx.x;
    const int tid = threadIdx.x;

    for (int e = tid; e < 64 * 256; e += 256) {
        const int cc = e >> 8, el = e & 255;
        cP[e] = g_Pref[((size_t)(b * 64 + cc) * 64 + 63) * 256 + el];
    }
    for (int e = tid; e < 64 * 16; e += 256) {
        const int cc = e >> 4, el = e & 15;
        cq[e] = g_r[((size_t)(b * 64 + cc) * 64 + 63) * 16 + el];
    }
    __syncthreads();

    if (tid < 32) {
        const int i = tid & 15;
        float h = 0.0f;
        for (int cc = 0; cc < 64; ++cc) {
            if (tid < 16) g_H0[(b * 64 + cc) * 16 + i] = h;
            float acc = cq[cc * 16 + i];
            #pragma unroll
            for (int j = 0; j < 16; ++j) {
                const float hj = __shfl_sync(0xffffffffu, h, j);
                acc += cP[cc * 256 + i * 16 + j] * hj;
            }
            h = acc;
        }
    }
}

// ---------------------------------------------------------------------------
// K3: per chunk — h_t = Pref_t @ h0 + r_t (parallel), then
//     out[t,d] = sum_{n,k} (h[t,n]*x[t,k]) * W_C[k,(n,d)] + sum_n h[t,n] bC[n,d]
//     ("z-form": no per-n accumulator tile -> low regs -> 3 CTAs/SM)
// ---------------------------------------------------------------------------
__global__ __launch_bounds__(256, 3)
void k3_out(const float* __restrict__ x,
            const float* __restrict__ WC, const float* __restrict__ bC,
            float* __restrict__ out)
{
    __shared__ float sxT[64 * SXT];   // 64*68
    __shared__ float shT[16 * SHT];   // shT[n*SHT + t]
    __shared__ float sh0[16];

    const int c   = blockIdx.x;
    const int tid = threadIdx.x;
    const float* xc = x + (size_t)c * CH * D;

    load_xT(xc, sxT, tid);
    if (tid < 16) sh0[tid] = g_H0[c * 16 + tid];
    __syncthreads();

    // h for every token, fully parallel; stored transposed shT[n][t]
    {
        const float* gP = g_Pref + (size_t)c * CH * 256;
        const float* gr = g_r    + (size_t)c * CH * 16;
        #pragma unroll
        for (int u = 0; u < 4; ++u) {
            const int e = tid + 256 * u;   // 0..1023
            const int t = e >> 4, n = e & 15;
            const float4* prow = (const float4*)(gP + t * 256 + n * 16);
            float acc = gr[e];
            #pragma unroll
            for (int jq = 0; jq < 4; ++jq) {
                const float4 p  = prow[jq];
                const float4 h0 = *(const float4*)&sh0[jq * 4];
                acc += p.x * h0.x + p.y * h0.y + p.z * h0.z + p.w * h0.w;
            }
            shT[n * SHT + t] = acc;
        }
    }
    __syncthreads();

    // output: thread owns 4 tokens (2 pairs) x 4 d's.  dq = tid&15, tg = tid>>4
    {
        const int dq = tid & 15;
        const int tg = tid >> 4;
        const int tb = tg * 4;
        const float4* WC4 = (const float4*)WC;
        u64 oacc[2][4];
        #pragma unroll
        for (int p = 0; p < 2; ++p)
            #pragma unroll
            for (int cc = 0; cc < 4; ++cc) oacc[p][cc] = 0ull;

        for (int n = 0; n < 16; ++n) {
            const int widx = n * 16 + dq;
            // h pair for this n / token pair
            u64 hp[2];
            hp[0] = *(const u64*)&shT[n * SHT + tb];
            hp[1] = *(const u64*)&shT[n * SHT + tb + 2];
            // bias fold: oacc += hp * bC[n, d]
            {
                const float4 bcn = *(const float4*)&bC[n * 64 + dq * 4];
                const u64 bx = pack2(bcn.x, bcn.x), by = pack2(bcn.y, bcn.y);
                const u64 bz = pack2(bcn.z, bcn.z), bw = pack2(bcn.w, bcn.w);
                #pragma unroll
                for (int p = 0; p < 2; ++p) {
                    oacc[p][0] = fma2(hp[p], bx, oacc[p][0]);
                    oacc[p][1] = fma2(hp[p], by, oacc[p][1]);
                    oacc[p][2] = fma2(hp[p], bz, oacc[p][2]);
                    oacc[p][3] = fma2(hp[p], bw, oacc[p][3]);
                }
            }
            for (int kg = 0; kg < 16; ++kg) {
                #pragma unroll
                for (int j = 0; j < 4; ++j) {
                    const int k = kg * 4 + j;
                    const float4 w = WC4[k * 256 + widx];
                    const u64 wpx = pack2(w.x, w.x);
                    const u64 wpy = pack2(w.y, w.y);
                    const u64 wpz = pack2(w.z, w.z);
                    const u64 wpw = pack2(w.w, w.w);
                    const ulonglong2 xa = *(const ulonglong2*)&sxT[k * SXT + tb];
                    const u64 z0 = mul2(hp[0], xa.x);
                    const u64 z1 = mul2(hp[1], xa.y);
                    oacc[0][0] = fma2(z0, wpx, oacc[0][0]);
                    oacc[0][1] = fma2(z0, wpy, oacc[0][1]);
                    oacc[0][2] = fma2(z0, wpz, oacc[0][2]);
                    oacc[0][3] = fma2(z0, wpw, oacc[0][3]);
                    oacc[1][0] = fma2(z1, wpx, oacc[1][0]);
                    oacc[1][1] = fma2(z1, wpy, oacc[1][1]);
                    oacc[1][2] = fma2(z1, wpz, oacc[1][2]);
                    oacc[1][3] = fma2(z1, wpw, oacc[1][3]);
                }
            }
        }
        // store: unpack token pairs into float4 rows
        #pragma unroll
        for (int p = 0; p < 2; ++p) {
            float4 o0, o1;
            unpack2(oacc[p][0], o0.x, o1.x);
            unpack2(oacc[p][1], o0.y, o1.y);
            unpack2(oacc[p][2], o0.z, o1.z);
            unpack2(oacc[p][3], o0.w, o1.w);
            const int t0 = tb + 2 * p;
            *(float4*)&out[((size_t)c * CH + t0)     * 64 + dq * 4] = o0;
            *(float4*)&out[((size_t)c * CH + t0 + 1) * 64 + dq * 4] = o1;
        }
    }
}

// ---------------------------------------------------------------------------
extern "C" void kernel_launch(void* const* d_in, const int* in_sizes, int n_in,
                              void* d_out, int out_size)
{
    const float* x  = (const float*)d_in[0];
    const float* WA = (const float*)d_in[1];
    const float* bA = (const float*)d_in[2];
    const float* WB = (const float*)d_in[3];
    const float* bB = (const float*)d_in[4];
    const float* WC = (const float*)d_in[5];
    const float* bC = (const float*)d_in[6];
    float* out = (float*)d_out;

    const int smemS = (64 * 256 + 64 * 16 + 512 + 32) * 4;             // 71808
    const int smem2 = (64 * 256 + 64 * 16) * 4;                        // 69632

    cudaFuncSetAttribute(kS,       cudaFuncAttributeMaxDynamicSharedMemorySize, smemS);
    cudaFuncSetAttribute(k2_chain, cudaFuncAttributeMaxDynamicSharedMemorySize, smem2);

    kA      <<<NCHUNKS, 256>>>(x, WA, bA);
    kB      <<<NCHUNKS, 256>>>(x, WB, bB);
    kS      <<<NCHUNKS, 256, smemS>>>();
    k2_chain<<<B,       256, smem2>>>();
    k3_out  <<<NCHUNKS, 256>>>(x, WC, bC, out);
}

// round 12
// speedup vs baseline: 1.0073x; 1.0073x over previous
#include <cuda_runtime.h>
#include <cuda_bf16.h>
#include <cstdint>

// Problem constants
constexpr int B  = 8;
constexpr int S  = 4096;
constexpr int D  = 64;
constexpr int DS = 16;
constexpr int CH = 64;                       // chunk length (tokens)
constexpr int NCHUNKS = B * S / CH;          // 512
constexpr int NTOK = B * S;                  // 32768

constexpr int SXT = 68;                      // sxT row stride (floats), 16B rows
constexpr int SX2 = 65;                      // sx2 (token-major) row stride
constexpr int SHT = 66;                      // shT row stride

// Scratch
__device__ float g_Pref[NTOK * DS * DS];     // 33.5 MB per-token prefix transitions
__device__ float g_r  [NTOK * DS];           //  2  MB per-token prefix offsets
__device__ float g_H0 [NCHUNKS * DS];        // state at each chunk start

// ---------------------------------------------------------------------------
// packed f32x2 helpers (SASS FFMA2 — PTX-only path on sm_103a)
// ---------------------------------------------------------------------------
using u64 = unsigned long long;

__device__ __forceinline__ u64 pack2(float lo, float hi) {
    u64 r; asm("mov.b64 %0, {%1, %2};" : "=l"(r) : "f"(lo), "f"(hi)); return r;
}
__device__ __forceinline__ void unpack2(u64 v, float& lo, float& hi) {
    asm("mov.b64 {%0, %1}, %2;" : "=f"(lo), "=f"(hi) : "l"(v));
}
__device__ __forceinline__ u64 fma2(u64 a, u64 b, u64 c) {
    u64 d; asm("fma.rn.f32x2 %0, %1, %2, %3;" : "=l"(d) : "l"(a), "l"(b), "l"(c)); return d;
}
__device__ __forceinline__ u64 mul2(u64 a, u64 b) {
    u64 d; asm("mul.rn.f32x2 %0, %1, %2;" : "=l"(d) : "l"(a), "l"(b)); return d;
}
__device__ __forceinline__ u64 add2(u64 a, u64 b) {
    u64 d; asm("add.rn.f32x2 %0, %1, %2;" : "=l"(d) : "l"(a), "l"(b)); return d;
}

// transpose-load a 64x64 token-major x chunk into sxT[k*SXT + t]
__device__ __forceinline__ void load_xT(const float* __restrict__ xc, float* sxT, int tid) {
    for (int e = tid; e < 2048; e += 256) {
        const int k  = e & 63;
        const int tp = e >> 6;                 // token pair 0..31
        const float a = xc[(2 * tp)     * 64 + k];
        const float b = xc[(2 * tp + 1) * 64 + k];
        *(float2*)&sxT[k * SXT + 2 * tp] = make_float2(a, b);
    }
}

// ---------------------------------------------------------------------------
// K1: fused per chunk — A projection, Bx (16-token tiles), serial chunk scan
// smem: sxT[64*68] sx2[64*65] sA[64*256] sBx[64*16] sP[2*256] sq[2*16]
//     = 17408 + 16640 + 65536 + 4096 + 2048 + 128 = 105856 B  -> 2 CTAs/SM
// ---------------------------------------------------------------------------
__global__ __launch_bounds__(256, 2)
void k1_proj_scan(const float* __restrict__ x,
                  const float* __restrict__ WA, const float* __restrict__ bA,
                  const float* __restrict__ WB, const float* __restrict__ bB)
{
    extern __shared__ float sm[];
    float* sxT = sm;                  // 64*68
    float* sx2 = sxT + 64 * SXT;      // 64*65 token-major
    float* sA  = sx2 + 64 * SX2;      // 64*256
    float* sBx = sA  + 64 * 256;      // 64*16
    float* sP  = sBx + 64 * 16;       // 2*256
    float* sq  = sP  + 512;           // 2*16

    const int c   = blockIdx.x;
    const int tid = threadIdx.x;
    const float* xc = x + (size_t)c * CH * D;

    load_xT(xc, sxT, tid);
    for (int e = tid; e < CH * D; e += 256)
        sx2[(e >> 6) * SX2 + (e & 63)] = xc[e];
    __syncthreads();

    // ---- Phase A: A = x @ W_A + b_A.  Thread owns column i; tokens paired.
    {
        const int i = tid;
        const float bias = bA[i];
        for (int half = 0; half < 2; ++half) {
            u64 acc[16];
            #pragma unroll
            for (int p = 0; p < 16; ++p) acc[p] = pack2(bias, bias);
            float w0 = WA[0 * 256 + i];
            float w1 = WA[1 * 256 + i];
            #pragma unroll 4
            for (int k = 0; k < 64; ++k) {
                const float w2 = (k < 62) ? WA[(k + 2) * 256 + i] : 0.0f;
                const u64 wp = pack2(w0, w0);
                const float* xrow = &sxT[k * SXT + half * 32];
                #pragma unroll
                for (int q = 0; q < 8; ++q) {
                    const ulonglong2 xv = *(const ulonglong2*)&xrow[q * 4];
                    acc[2 * q]     = fma2(xv.x, wp, acc[2 * q]);
                    acc[2 * q + 1] = fma2(xv.y, wp, acc[2 * q + 1]);
                }
                w0 = w1; w1 = w2;
            }
            #pragma unroll
            for (int p = 0; p < 16; ++p) {
                float lo, hi; unpack2(acc[p], lo, hi);
                const int t0 = half * 32 + 2 * p;
                sA[t0 * 256 + i]       = lo;
                sA[(t0 + 1) * 256 + i] = hi;
            }
        }
    }

    // ---- Phase B: Bx[t,n] = sum_d (x@W_B + b_B)[t,n,d] * x[t,d]
    //      16-token tiles (halves W_B restreaming). n = tid>>4, dq = tid&15.
    {
        const int n  = tid >> 4;
        const int dq = tid & 15;
        const float4 bb = *(const float4*)&bB[n * 64 + dq * 4];
        const float bbc[4] = {bb.x, bb.y, bb.z, bb.w};
        const float4* WB4 = (const float4*)WB;
        const int widx = n * 16 + dq;

        for (int tt = 0; tt < 4; ++tt) {
            const int base = tt * 16;          // tokens base..base+15 (8 pairs)
            u64 acc[8][4];
            #pragma unroll
            for (int p = 0; p < 8; ++p)
                #pragma unroll
                for (int cc = 0; cc < 4; ++cc) acc[p][cc] = pack2(bbc[cc], bbc[cc]);

            float4 w[4];
            #pragma unroll
            for (int j = 0; j < 4; ++j) w[j] = WB4[j * 256 + widx];
            for (int kg = 0; kg < 16; ++kg) {
                float4 wn[4];
                const int nk = (kg < 15) ? (kg + 1) * 4 : 0;
                #pragma unroll
                for (int j = 0; j < 4; ++j) wn[j] = WB4[(nk + j) * 256 + widx];
                #pragma unroll
                for (int j = 0; j < 4; ++j) {
                    const int k = kg * 4 + j;
                    const u64 wpx = pack2(w[j].x, w[j].x);
                    const u64 wpy = pack2(w[j].y, w[j].y);
                    const u64 wpz = pack2(w[j].z, w[j].z);
                    const u64 wpw = pack2(w[j].w, w[j].w);
                    const float* xr = &sxT[k * SXT + base];
                    const ulonglong2 x0 = *(const ulonglong2*)&xr[0];
                    const ulonglong2 x1 = *(const ulonglong2*)&xr[4];
                    const ulonglong2 x2 = *(const ulonglong2*)&xr[8];
                    const ulonglong2 x3 = *(const ulonglong2*)&xr[12];
                    const u64 xp[8] = {x0.x, x0.y, x1.x, x1.y, x2.x, x2.y, x3.x, x3.y};
                    #pragma unroll
                    for (int p = 0; p < 8; ++p) {
                        acc[p][0] = fma2(xp[p], wpx, acc[p][0]);
                        acc[p][1] = fma2(xp[p], wpy, acc[p][1]);
                        acc[p][2] = fma2(xp[p], wpz, acc[p][2]);
                        acc[p][3] = fma2(xp[p], wpw, acc[p][3]);
                    }
                }
                #pragma unroll
                for (int j = 0; j < 4; ++j) w[j] = wn[j];
            }
            // epilogue: dot with x over this thread's 4 d's (token-major sx2,
            // 2-way conflicts), then reduce across the 16 dq lanes
            #pragma unroll
            for (int p = 0; p < 8; ++p) {
                const int t0 = base + 2 * p;
                u64 v;
                #pragma unroll
                for (int cc = 0; cc < 4; ++cc) {
                    const int d = dq * 4 + cc;
                    const u64 xpair = pack2(sx2[t0 * SX2 + d], sx2[(t0 + 1) * SX2 + d]);
                    v = (cc == 0) ? mul2(acc[p][0], xpair) : fma2(acc[p][cc], xpair, v);
                }
                v = add2(v, __shfl_xor_sync(0xffffffffu, v, 8, 16));
                v = add2(v, __shfl_xor_sync(0xffffffffu, v, 4, 16));
                v = add2(v, __shfl_xor_sync(0xffffffffu, v, 2, 16));
                v = add2(v, __shfl_xor_sync(0xffffffffu, v, 1, 16));
                if (dq == 0) {
                    float lo, hi; unpack2(v, lo, hi);
                    sBx[t0 * 16 + n]       = lo;
                    sBx[(t0 + 1) * 16 + n] = hi;
                }
            }
        }
    }

    // ---- Phase C: serial chunk scan, emitting every prefix (Pref_t, r_t).
    {
        const int pi = tid >> 4, pj = tid & 15;
        sP[tid] = (pi == pj) ? 1.0f : 0.0f;
        if (tid < 16) sq[tid] = 0.0f;
        __syncthreads();

        float* gP = g_Pref + (size_t)c * CH * 256;
        float* gr = g_r    + (size_t)c * CH * 16;
        int cur = 0;
        for (int t = 0; t < CH; ++t) {
            const float* At = &sA[t * 256];
            float np0 = 0.0f, np1 = 0.0f;
            #pragma unroll
            for (int k = 0; k < 16; k += 2) {
                np0 += At[pi * 16 + k]     * sP[cur * 256 + k * 16 + pj];
                np1 += At[pi * 16 + k + 1] * sP[cur * 256 + (k + 1) * 16 + pj];
            }
            const float np = np0 + np1;
            float nq = 0.0f;
            if (tid < 16) {
                nq = sBx[t * 16 + tid];
                #pragma unroll
                for (int k = 0; k < 16; ++k)
                    nq += At[tid * 16 + k] * sq[cur * 16 + k];
            }
            sP[(cur ^ 1) * 256 + tid] = np;
            if (tid < 16) sq[(cur ^ 1) * 16 + tid] = nq;
            gP[t * 256 + tid] = np;                    // fire-and-forget STG
            if (tid < 16) gr[t * 16 + tid] = nq;
            cur ^= 1;
            __syncthreads();
        }
    }
}

// ---------------------------------------------------------------------------
// K2: per batch — serial scan over 64 chunk-final (P,q) pairs -> g_H0
//     split-j half-warp dot (8 shfl + 8 FMA) + butterfly combine per step.
// ---------------------------------------------------------------------------
__global__ __launch_bounds__(256)
void k2_chain(void)
{
    extern __shared__ float sm[];
    float* cP = sm;            // 64*256
    float* cq = cP + 64 * 256; // 64*16

    const int b   = blockIdx.x;
    const int tid = threadIdx.x;

    for (int e = tid; e < 64 * 256; e += 256) {
        const int cc = e >> 8, el = e & 255;
        cP[e] = g_Pref[((size_t)(b * 64 + cc) * 64 + 63) * 256 + el];
    }
    for (int e = tid; e < 64 * 16; e += 256) {
        const int cc = e >> 4, el = e & 15;
        cq[e] = g_r[((size_t)(b * 64 + cc) * 64 + 63) * 16 + el];
    }
    __syncthreads();

    if (tid < 32) {
        const int lane = tid;
        const int i    = lane & 15;
        const int hb   = (lane >> 4) * 8;      // this half's j-base (0 or 8)
        const int hsel = lane & 16;            // shfl source half selector
        float h = 0.0f;                         // h_i replicated in both halves
        for (int cc = 0; cc < 64; ++cc) {
            if (lane < 16) g_H0[(b * 64 + cc) * 16 + i] = h;
            const float4 r0 = *(const float4*)&cP[cc * 256 + i * 16 + hb];
            const float4 r1 = *(const float4*)&cP[cc * 256 + i * 16 + hb + 4];
            float p0, p1;
            p0  = r0.x * __shfl_sync(0xffffffffu, h, hsel | (hb + 0));
            p1  = r0.y * __shfl_sync(0xffffffffu, h, hsel | (hb + 1));
            p0 += r0.z * __shfl_sync(0xffffffffu, h, hsel | (hb + 2));
            p1 += r0.w * __shfl_sync(0xffffffffu, h, hsel | (hb + 3));
            p0 += r1.x * __shfl_sync(0xffffffffu, h, hsel | (hb + 4));
            p1 += r1.y * __shfl_sync(0xffffffffu, h, hsel | (hb + 5));
            p0 += r1.z * __shfl_sync(0xffffffffu, h, hsel | (hb + 6));
            p1 += r1.w * __shfl_sync(0xffffffffu, h, hsel | (hb + 7));
            float part = p0 + p1;
            part += __shfl_xor_sync(0xffffffffu, part, 16);   // combine halves
            h = cq[cc * 16 + i] + part;
        }
    }
}

// ---------------------------------------------------------------------------
// K3: per chunk — h_t = Pref_t @ h0 + r_t (parallel), then
//     out = (x@W_C)^T h + (h^T bC), token-paired f32x2.  3 CTAs/SM.
// smem: sxT[64*68] shT[16*66] sh0[16] = 21696 B
// ---------------------------------------------------------------------------
__global__ __launch_bounds__(256, 3)
void k3_out(const float* __restrict__ x,
            const float* __restrict__ WC, const float* __restrict__ bC,
            float* __restrict__ out)
{
    __shared__ float sxT[64 * SXT];
    __shared__ float shT[16 * SHT];   // shT[n*SHT + t]
    __shared__ float sh0[16];

    const int c   = blockIdx.x;
    const int tid = threadIdx.x;
    const float* xc = x + (size_t)c * CH * D;

    load_xT(xc, sxT, tid);
    if (tid < 16) sh0[tid] = g_H0[c * 16 + tid];
    __syncthreads();

    // h for every token, fully parallel; stored transposed shT[n][t]
    {
        const float* gP = g_Pref + (size_t)c * CH * 256;
        const float* gr = g_r    + (size_t)c * CH * 16;
        #pragma unroll
        for (int u = 0; u < 4; ++u) {
            const int e = tid + 256 * u;   // 0..1023
            const int t = e >> 4, n = e & 15;
            const float4* prow = (const float4*)(gP + t * 256 + n * 16);
            float acc = gr[e];
            #pragma unroll
            for (int jq = 0; jq < 4; ++jq) {
                const float4 p  = prow[jq];
                const float4 h0 = *(const float4*)&sh0[jq * 4];
                acc += p.x * h0.x + p.y * h0.y + p.z * h0.z + p.w * h0.w;
            }
            shT[n * SHT + t] = acc;
        }
    }
    __syncthreads();

    // output: thread owns 4 tokens (2 pairs) x 4 d's.  dq = tid&15, tg = tid>>4
    {
        const int dq = tid & 15;
        const int tg = tid >> 4;
        const int tb = tg * 4;
        const float4* WC4 = (const float4*)WC;
        u64 oacc[2][4];

        // bias fold first (small loop): oacc[p][cc] = sum_n h[n] * bC[n,d]
        {
            const u64 h0p0 = *(const u64*)&shT[0 * SHT + tb];
            const u64 h0p1 = *(const u64*)&shT[0 * SHT + tb + 2];
            const float4 b0 = *(const float4*)&bC[0 * 64 + dq * 4];
            oacc[0][0] = mul2(h0p0, pack2(b0.x, b0.x));
            oacc[0][1] = mul2(h0p0, pack2(b0.y, b0.y));
            oacc[0][2] = mul2(h0p0, pack2(b0.z, b0.z));
            oacc[0][3] = mul2(h0p0, pack2(b0.w, b0.w));
            oacc[1][0] = mul2(h0p1, pack2(b0.x, b0.x));
            oacc[1][1] = mul2(h0p1, pack2(b0.y, b0.y));
            oacc[1][2] = mul2(h0p1, pack2(b0.z, b0.z));
            oacc[1][3] = mul2(h0p1, pack2(b0.w, b0.w));
            for (int n = 1; n < 16; ++n) {
                const u64 hp0 = *(const u64*)&shT[n * SHT + tb];
                const u64 hp1 = *(const u64*)&shT[n * SHT + tb + 2];
                const float4 bcn = *(const float4*)&bC[n * 64 + dq * 4];
                oacc[0][0] = fma2(hp0, pack2(bcn.x, bcn.x), oacc[0][0]);
                oacc[0][1] = fma2(hp0, pack2(bcn.y, bcn.y), oacc[0][1]);
                oacc[0][2] = fma2(hp0, pack2(bcn.z, bcn.z), oacc[0][2]);
                oacc[0][3] = fma2(hp0, pack2(bcn.w, bcn.w), oacc[0][3]);
                oacc[1][0] = fma2(hp1, pack2(bcn.x, bcn.x), oacc[1][0]);
                oacc[1][1] = fma2(hp1, pack2(bcn.y, bcn.y), oacc[1][1]);
                oacc[1][2] = fma2(hp1, pack2(bcn.z, bcn.z), oacc[1][2]);
                oacc[1][3] = fma2(hp1, pack2(bcn.w, bcn.w), oacc[1][3]);
            }
        }

        for (int n = 0; n < 16; ++n) {
            const int widx = n * 16 + dq;
            u64 cm[2][4];
            #pragma unroll
            for (int p = 0; p < 2; ++p)
                #pragma unroll
                for (int cc = 0; cc < 4; ++cc) cm[p][cc] = 0ull;

            for (int kg = 0; kg < 16; ++kg) {
                #pragma unroll
                for (int j = 0; j < 4; ++j) {
                    const int k = kg * 4 + j;
                    const float4 w = WC4[k * 256 + widx];
                    const u64 wpx = pack2(w.x, w.x);
                    const u64 wpy = pack2(w.y, w.y);
                    const u64 wpz = pack2(w.z, w.z);
                    const u64 wpw = pack2(w.w, w.w);
                    const ulonglong2 xa = *(const ulonglong2*)&sxT[k * SXT + tb];
                    cm[0][0] = fma2(xa.x, wpx, cm[0][0]);
                    cm[0][1] = fma2(xa.x, wpy, cm[0][1]);
                    cm[0][2] = fma2(xa.x, wpz, cm[0][2]);
                    cm[0][3] = fma2(xa.x, wpw, cm[0][3]);
                    cm[1][0] = fma2(xa.y, wpx, cm[1][0]);
                    cm[1][1] = fma2(xa.y, wpy, cm[1][1]);
                    cm[1][2] = fma2(xa.y, wpz, cm[1][2]);
                    cm[1][3] = fma2(xa.y, wpw, cm[1][3]);
                }
            }
            // fold with h_n for this token pair
            const u64 hp0 = *(const u64*)&shT[n * SHT + tb];
            const u64 hp1 = *(const u64*)&shT[n * SHT + tb + 2];
            #pragma unroll
            for (int cc = 0; cc < 4; ++cc) {
                oacc[0][cc] = fma2(hp0, cm[0][cc], oacc[0][cc]);
                oacc[1][cc] = fma2(hp1, cm[1][cc], oacc[1][cc]);
            }
        }
        // store: unpack token pairs into float4 rows
        #pragma unroll
        for (int p = 0; p < 2; ++p) {
            float4 o0, o1;
            unpack2(oacc[p][0], o0.x, o1.x);
            unpack2(oacc[p][1], o0.y, o1.y);
            unpack2(oacc[p][2], o0.z, o1.z);
            unpack2(oacc[p][3], o0.w, o1.w);
            const int t0 = tb + 2 * p;
            *(float4*)&out[((size_t)c * CH + t0)     * 64 + dq * 4] = o0;
            *(float4*)&out[((size_t)c * CH + t0 + 1) * 64 + dq * 4] = o1;
        }
    }
}

// ---------------------------------------------------------------------------
extern "C" void kernel_launch(void* const* d_in, const int* in_sizes, int n_in,
                              void* d_out, int out_size)
{
    const float* x  = (const float*)d_in[0];
    const float* WA = (const float*)d_in[1];
    const float* bA = (const float*)d_in[2];
    const float* WB = (const float*)d_in[3];
    const float* bB = (const float*)d_in[4];
    const float* WC = (const float*)d_in[5];
    const float* bC = (const float*)d_in[6];
    float* out = (float*)d_out;

    const int smem1 = (64 * SXT + 64 * SX2 + 64 * 256 + 64 * 16 + 512 + 32) * 4; // 105856
    const int smem2 = (64 * 256 + 64 * 16) * 4;                                  // 69632

    cudaFuncSetAttribute(k1_proj_scan, cudaFuncAttributeMaxDynamicSharedMemorySize, smem1);
    cudaFuncSetAttribute(k2_chain,     cudaFuncAttributeMaxDynamicSharedMemorySize, smem2);

    k1_proj_scan<<<NCHUNKS, 256, smem1>>>(x, WA, bA, WB, bB);
    k2_chain    <<<B,       256, smem2>>>();
    k3_out      <<<NCHUNKS, 256>>>(x, WC, bC, out);
}

// round 14
// speedup vs baseline: 1.1530x; 1.1447x over previous
#include <cuda_runtime.h>
#include <cuda_bf16.h>
#include <cstdint>

// Problem constants
constexpr int B  = 8;
constexpr int S  = 4096;
constexpr int D  = 64;
constexpr int DS = 16;
constexpr int CH = 64;                       // chunk length (tokens)
constexpr int NCHUNKS = B * S / CH;          // 512
constexpr int NTOK = B * S;                  // 32768

constexpr int SXT = 68;                      // sxT row stride (floats), 16B rows
constexpr int SX2 = 65;                      // sx2 (token-major) row stride
constexpr int SHT = 66;                      // shT row stride

// Scratch
__device__ float g_Pref[NTOK * DS * DS];     // 33.5 MB per-token prefix transitions
__device__ float g_r  [NTOK * DS];           //  2  MB per-token prefix offsets
__device__ float g_H0 [NCHUNKS * DS];        // state at each chunk start

// ---------------------------------------------------------------------------
// packed f32x2 helpers (SASS FFMA2 — PTX-only path on sm_103a)
// ---------------------------------------------------------------------------
using u64 = unsigned long long;

__device__ __forceinline__ u64 pack2(float lo, float hi) {
    u64 r; asm("mov.b64 %0, {%1, %2};" : "=l"(r) : "f"(lo), "f"(hi)); return r;
}
__device__ __forceinline__ void unpack2(u64 v, float& lo, float& hi) {
    asm("mov.b64 {%0, %1}, %2;" : "=f"(lo), "=f"(hi) : "l"(v));
}
__device__ __forceinline__ u64 fma2(u64 a, u64 b, u64 c) {
    u64 d; asm("fma.rn.f32x2 %0, %1, %2, %3;" : "=l"(d) : "l"(a), "l"(b), "l"(c)); return d;
}
__device__ __forceinline__ u64 mul2(u64 a, u64 b) {
    u64 d; asm("mul.rn.f32x2 %0, %1, %2;" : "=l"(d) : "l"(a), "l"(b)); return d;
}
__device__ __forceinline__ u64 add2(u64 a, u64 b) {
    u64 d; asm("add.rn.f32x2 %0, %1, %2;" : "=l"(d) : "l"(a), "l"(b)); return d;
}

// transpose-load a 64x64 token-major x chunk into sxT[k*SXT + t]
__device__ __forceinline__ void load_xT(const float* __restrict__ xc, float* sxT, int tid) {
    for (int e = tid; e < 2048; e += 256) {
        const int k  = e & 63;
        const int tp = e >> 6;                 // token pair 0..31
        const float a = xc[(2 * tp)     * 64 + k];
        const float b = xc[(2 * tp + 1) * 64 + k];
        *(float2*)&sxT[k * SXT + 2 * tp] = make_float2(a, b);
    }
}

// ---------------------------------------------------------------------------
// K1: fused per chunk — A projection, Bx (16-token tiles), serial chunk scan
// smem: sxT[64*68] sx2[64*65] sA[64*256] sBx[64*16] sP[2*256] sq[2*16]
//     = 105856 B  -> 2 CTAs/SM
// ---------------------------------------------------------------------------
__global__ __launch_bounds__(256, 2)
void k1_proj_scan(const float* __restrict__ x,
                  const float* __restrict__ WA, const float* __restrict__ bA,
                  const float* __restrict__ WB, const float* __restrict__ bB)
{
    extern __shared__ float sm[];
    float* sxT = sm;                  // 64*68
    float* sx2 = sxT + 64 * SXT;      // 64*65 token-major
    float* sA  = sx2 + 64 * SX2;      // 64*256
    float* sBx = sA  + 64 * 256;      // 64*16
    float* sP  = sBx + 64 * 16;       // 2*256
    float* sq  = sP  + 512;           // 2*16

    const int c   = blockIdx.x;
    const int tid = threadIdx.x;
    const float* xc = x + (size_t)c * CH * D;

    load_xT(xc, sxT, tid);
    for (int e = tid; e < CH * D; e += 256)
        sx2[(e >> 6) * SX2 + (e & 63)] = xc[e];
    __syncthreads();

    // ---- Phase A: A = x @ W_A + b_A.  Thread owns column i; tokens paired.
    {
        const int i = tid;
        const float bias = bA[i];
        for (int half = 0; half < 2; ++half) {
            u64 acc[16];
            #pragma unroll
            for (int p = 0; p < 16; ++p) acc[p] = pack2(bias, bias);
            float w0 = WA[0 * 256 + i];
            float w1 = WA[1 * 256 + i];
            #pragma unroll 4
            for (int k = 0; k < 64; ++k) {
                const float w2 = (k < 62) ? WA[(k + 2) * 256 + i] : 0.0f;
                const u64 wp = pack2(w0, w0);
                const float* xrow = &sxT[k * SXT + half * 32];
                #pragma unroll
                for (int q = 0; q < 8; ++q) {
                    const ulonglong2 xv = *(const ulonglong2*)&xrow[q * 4];
                    acc[2 * q]     = fma2(xv.x, wp, acc[2 * q]);
                    acc[2 * q + 1] = fma2(xv.y, wp, acc[2 * q + 1]);
                }
                w0 = w1; w1 = w2;
            }
            #pragma unroll
            for (int p = 0; p < 16; ++p) {
                float lo, hi; unpack2(acc[p], lo, hi);
                const int t0 = half * 32 + 2 * p;
                sA[t0 * 256 + i]       = lo;
                sA[(t0 + 1) * 256 + i] = hi;
            }
        }
    }

    // ---- Phase B: Bx[t,n] = sum_d (x@W_B + b_B)[t,n,d] * x[t,d]
    //      16-token tiles (halves W_B restreaming). n = tid>>4, dq = tid&15.
    {
        const int n  = tid >> 4;
        const int dq = tid & 15;
        const float4 bb = *(const float4*)&bB[n * 64 + dq * 4];
        const float bbc[4] = {bb.x, bb.y, bb.z, bb.w};
        const float4* WB4 = (const float4*)WB;
        const int widx = n * 16 + dq;

        for (int tt = 0; tt < 4; ++tt) {
            const int base = tt * 16;          // tokens base..base+15 (8 pairs)
            u64 acc[8][4];
            #pragma unroll
            for (int p = 0; p < 8; ++p)
                #pragma unroll
                for (int cc = 0; cc < 4; ++cc) acc[p][cc] = pack2(bbc[cc], bbc[cc]);

            float4 w[4];
            #pragma unroll
            for (int j = 0; j < 4; ++j) w[j] = WB4[j * 256 + widx];
            for (int kg = 0; kg < 16; ++kg) {
                float4 wn[4];
                const int nk = (kg < 15) ? (kg + 1) * 4 : 0;
                #pragma unroll
                for (int j = 0; j < 4; ++j) wn[j] = WB4[(nk + j) * 256 + widx];
                #pragma unroll
                for (int j = 0; j < 4; ++j) {
                    const int k = kg * 4 + j;
                    const u64 wpx = pack2(w[j].x, w[j].x);
                    const u64 wpy = pack2(w[j].y, w[j].y);
                    const u64 wpz = pack2(w[j].z, w[j].z);
                    const u64 wpw = pack2(w[j].w, w[j].w);
                    const float* xr = &sxT[k * SXT + base];
                    const ulonglong2 x0 = *(const ulonglong2*)&xr[0];
                    const ulonglong2 x1 = *(const ulonglong2*)&xr[4];
                    const ulonglong2 x2 = *(const ulonglong2*)&xr[8];
                    const ulonglong2 x3 = *(const ulonglong2*)&xr[12];
                    const u64 xp[8] = {x0.x, x0.y, x1.x, x1.y, x2.x, x2.y, x3.x, x3.y};
                    #pragma unroll
                    for (int p = 0; p < 8; ++p) {
                        acc[p][0] = fma2(xp[p], wpx, acc[p][0]);
                        acc[p][1] = fma2(xp[p], wpy, acc[p][1]);
                        acc[p][2] = fma2(xp[p], wpz, acc[p][2]);
                        acc[p][3] = fma2(xp[p], wpw, acc[p][3]);
                    }
                }
                #pragma unroll
                for (int j = 0; j < 4; ++j) w[j] = wn[j];
            }
            // epilogue: dot with x over this thread's 4 d's (token-major sx2),
            // then reduce across the 16 dq lanes
            #pragma unroll
            for (int p = 0; p < 8; ++p) {
                const int t0 = base + 2 * p;
                u64 v;
                #pragma unroll
                for (int cc = 0; cc < 4; ++cc) {
                    const int d = dq * 4 + cc;
                    const u64 xpair = pack2(sx2[t0 * SX2 + d], sx2[(t0 + 1) * SX2 + d]);
                    v = (cc == 0) ? mul2(acc[p][0], xpair) : fma2(acc[p][cc], xpair, v);
                }
                v = add2(v, __shfl_xor_sync(0xffffffffu, v, 8, 16));
                v = add2(v, __shfl_xor_sync(0xffffffffu, v, 4, 16));
                v = add2(v, __shfl_xor_sync(0xffffffffu, v, 2, 16));
                v = add2(v, __shfl_xor_sync(0xffffffffu, v, 1, 16));
                if (dq == 0) {
                    float lo, hi; unpack2(v, lo, hi);
                    sBx[t0 * 16 + n]       = lo;
                    sBx[(t0 + 1) * 16 + n] = hi;
                }
            }
        }
    }

    // ---- Phase C: serial chunk scan, emitting every prefix (Pref_t, r_t).
    {
        const int pi = tid >> 4, pj = tid & 15;
        sP[tid] = (pi == pj) ? 1.0f : 0.0f;
        if (tid < 16) sq[tid] = 0.0f;
        __syncthreads();

        float* gP = g_Pref + (size_t)c * CH * 256;
        float* gr = g_r    + (size_t)c * CH * 16;
        int cur = 0;
        for (int t = 0; t < CH; ++t) {
            const float* At = &sA[t * 256];
            float np0 = 0.0f, np1 = 0.0f;
            #pragma unroll
            for (int k = 0; k < 16; k += 2) {
                np0 += At[pi * 16 + k]     * sP[cur * 256 + k * 16 + pj];
                np1 += At[pi * 16 + k + 1] * sP[cur * 256 + (k + 1) * 16 + pj];
            }
            const float np = np0 + np1;
            float nq = 0.0f;
            if (tid < 16) {
                nq = sBx[t * 16 + tid];
                #pragma unroll
                for (int k = 0; k < 16; ++k)
                    nq += At[tid * 16 + k] * sq[cur * 16 + k];
            }
            sP[(cur ^ 1) * 256 + tid] = np;
            if (tid < 16) sq[(cur ^ 1) * 16 + tid] = nq;
            gP[t * 256 + tid] = np;                    // fire-and-forget STG
            if (tid < 16) gr[t * 16 + tid] = nq;
            cur ^= 1;
            __syncthreads();
        }
    }
}

// ---------------------------------------------------------------------------
// K2: per batch — serial scan over 64 chunk-final (P,q) pairs -> g_H0
//     split-j half-warp dot (8 shfl + 8 FMA) + butterfly combine per step.
// ---------------------------------------------------------------------------
__global__ __launch_bounds__(256)
void k2_chain(void)
{
    extern __shared__ float sm[];
    float* cP = sm;            // 64*256
    float* cq = cP + 64 * 256; // 64*16

    const int b   = blockIdx.x;
    const int tid = threadIdx.x;

    for (int e = tid; e < 64 * 256; e += 256) {
        const int cc = e >> 8, el = e & 255;
        cP[e] = g_Pref[((size_t)(b * 64 + cc) * 64 + 63) * 256 + el];
    }
    for (int e = tid; e < 64 * 16; e += 256) {
        const int cc = e >> 4, el = e & 15;
        cq[e] = g_r[((size_t)(b * 64 + cc) * 64 + 63) * 16 + el];
    }
    __syncthreads();

    if (tid < 32) {
        const int lane = tid;
        const int i    = lane & 15;
        const int hb   = (lane >> 4) * 8;      // this half's j-base (0 or 8)
        const int hsel = lane & 16;            // shfl source half selector
        float h = 0.0f;                         // h_i replicated in both halves
        for (int cc = 0; cc < 64; ++cc) {
            if (lane < 16) g_H0[(b * 64 + cc) * 16 + i] = h;
            const float4 r0 = *(const float4*)&cP[cc * 256 + i * 16 + hb];
            const float4 r1 = *(const float4*)&cP[cc * 256 + i * 16 + hb + 4];
            float p0, p1;
            p0  = r0.x * __shfl_sync(0xffffffffu, h, hsel | (hb + 0));
            p1  = r0.y * __shfl_sync(0xffffffffu, h, hsel | (hb + 1));
            p0 += r0.z * __shfl_sync(0xffffffffu, h, hsel | (hb + 2));
            p1 += r0.w * __shfl_sync(0xffffffffu, h, hsel | (hb + 3));
            p0 += r1.x * __shfl_sync(0xffffffffu, h, hsel | (hb + 4));
            p1 += r1.y * __shfl_sync(0xffffffffu, h, hsel | (hb + 5));
            p0 += r1.z * __shfl_sync(0xffffffffu, h, hsel | (hb + 6));
            p1 += r1.w * __shfl_sync(0xffffffffu, h, hsel | (hb + 7));
            float part = p0 + p1;
            part += __shfl_xor_sync(0xffffffffu, part, 16);   // combine halves
            h = cq[cc * 16 + i] + part;
        }
    }
}

// ---------------------------------------------------------------------------
// K3 (R10 form): per chunk — h_t = Pref_t @ h0 + r_t (parallel), then
//     out = (x@W_C + b_C)^T h, token-paired f32x2, W_C double-buffered.
// smem: sxT[64*68] shT[16*66] sh0[16] = 21696 B ; 2 CTAs/SM (reg-limited)
// ---------------------------------------------------------------------------
__global__ __launch_bounds__(256, 2)
void k3_out(const float* __restrict__ x,
            const float* __restrict__ WC, const float* __restrict__ bC,
            float* __restrict__ out)
{
    __shared__ float sxT[64 * SXT];
    __shared__ float shT[16 * SHT];   // shT[n*SHT + t]
    __shared__ float sh0[16];

    const int c   = blockIdx.x;
    const int tid = threadIdx.x;
    const float* xc = x + (size_t)c * CH * D;

    load_xT(xc, sxT, tid);
    if (tid < 16) sh0[tid] = g_H0[c * 16 + tid];
    __syncthreads();

    // h for every token, fully parallel; stored transposed shT[n][t]
    {
        const float* gP = g_Pref + (size_t)c * CH * 256;
        const float* gr = g_r    + (size_t)c * CH * 16;
        #pragma unroll
        for (int u = 0; u < 4; ++u) {
            const int e = tid + 256 * u;   // 0..1023
            const int t = e >> 4, n = e & 15;
            const float4* prow = (const float4*)(gP + t * 256 + n * 16);
            float acc = gr[e];
            #pragma unroll
            for (int jq = 0; jq < 4; ++jq) {
                const float4 p  = prow[jq];
                const float4 h0 = *(const float4*)&sh0[jq * 4];
                acc += p.x * h0.x + p.y * h0.y + p.z * h0.z + p.w * h0.w;
            }
            shT[n * SHT + t] = acc;
        }
    }
    __syncthreads();

    // output: thread owns 4 tokens (2 pairs) x 4 d's.  dq = tid&15, tg = tid>>4
    {
        const int dq = tid & 15;
        const int tg = tid >> 4;
        const int tb = tg * 4;
        const float4* WC4 = (const float4*)WC;
        u64 oacc[2][4];
        #pragma unroll
        for (int p = 0; p < 2; ++p)
            #pragma unroll
            for (int cc = 0; cc < 4; ++cc) oacc[p][cc] = 0ull;

        for (int n = 0; n < 16; ++n) {
            const int widx = n * 16 + dq;
            const float4 bcn = *(const float4*)&bC[n * 64 + dq * 4];
            const float bcc[4] = {bcn.x, bcn.y, bcn.z, bcn.w};
            u64 cm[2][4];
            #pragma unroll
            for (int p = 0; p < 2; ++p)
                #pragma unroll
                for (int cc = 0; cc < 4; ++cc) cm[p][cc] = pack2(bcc[cc], bcc[cc]);

            float4 w[4];
            #pragma unroll
            for (int j = 0; j < 4; ++j) w[j] = WC4[j * 256 + widx];
            for (int kg = 0; kg < 16; ++kg) {
                float4 wn[4];
                const int nk = (kg < 15) ? (kg + 1) * 4 : 0;
                #pragma unroll
                for (int j = 0; j < 4; ++j) wn[j] = WC4[(nk + j) * 256 + widx];
                #pragma unroll
                for (int j = 0; j < 4; ++j) {
                    const int k = kg * 4 + j;
                    const u64 wpx = pack2(w[j].x, w[j].x);
                    const u64 wpy = pack2(w[j].y, w[j].y);
                    const u64 wpz = pack2(w[j].z, w[j].z);
                    const u64 wpw = pack2(w[j].w, w[j].w);
                    const ulonglong2 xa = *(const ulonglong2*)&sxT[k * SXT + tb];
                    const u64 xp[2] = {xa.x, xa.y};
                    #pragma unroll
                    for (int p = 0; p < 2; ++p) {
                        cm[p][0] = fma2(xp[p], wpx, cm[p][0]);
                        cm[p][1] = fma2(xp[p], wpy, cm[p][1]);
                        cm[p][2] = fma2(xp[p], wpz, cm[p][2]);
                        cm[p][3] = fma2(xp[p], wpw, cm[p][3]);
                    }
                }
                #pragma unroll
                for (int j = 0; j < 4; ++j) w[j] = wn[j];
            }
            // fold with h_n for this token pair
            #pragma unroll
            for (int p = 0; p < 2; ++p) {
                const u64 hp = *(const u64*)&shT[n * SHT + tb + 2 * p];
                #pragma unroll
                for (int cc = 0; cc < 4; ++cc)
                    oacc[p][cc] = fma2(hp, cm[p][cc], oacc[p][cc]);
            }
        }
        // store: unpack token pairs into float4 rows
        #pragma unroll
        for (int p = 0; p < 2; ++p) {
            float4 o0, o1;
            unpack2(oacc[p][0], o0.x, o1.x);
            unpack2(oacc[p][1], o0.y, o1.y);
            unpack2(oacc[p][2], o0.z, o1.z);
            unpack2(oacc[p][3], o0.w, o1.w);
            const int t0 = tb + 2 * p;
            *(float4*)&out[((size_t)c * CH + t0)     * 64 + dq * 4] = o0;
            *(float4*)&out[((size_t)c * CH + t0 + 1) * 64 + dq * 4] = o1;
        }
    }
}

// ---------------------------------------------------------------------------
extern "C" void kernel_launch(void* const* d_in, const int* in_sizes, int n_in,
                              void* d_out, int out_size)
{
    const float* x  = (const float*)d_in[0];
    const float* WA = (const float*)d_in[1];
    const float* bA = (const float*)d_in[2];
    const float* WB = (const float*)d_in[3];
    const float* bB = (const float*)d_in[4];
    const float* WC = (const float*)d_in[5];
    const float* bC = (const float*)d_in[6];
    float* out = (float*)d_out;

    const int smem1 = (64 * SXT + 64 * SX2 + 64 * 256 + 64 * 16 + 512 + 32) * 4; // 105856
    const int smem2 = (64 * 256 + 64 * 16) * 4;                                  // 69632

    cudaFuncSetAttribute(k1_proj_scan, cudaFuncAttributeMaxDynamicSharedMemorySize, smem1);
    cudaFuncSetAttribute(k2_chain,     cudaFuncAttributeMaxDynamicSharedMemorySize, smem2);

    k1_proj_scan<<<NCHUNKS, 256, smem1>>>(x, WA, bA, WB, bB);
    k2_chain    <<<B,       256, smem2>>>();
    k3_out      <<<NCHUNKS, 256>>>(x, WC, bC, out);
}

// round 16
// speedup vs baseline: 1.1985x; 1.0394x over previous
#include <cuda_runtime.h>
#include <cuda_bf16.h>
#include <cstdint>

// Problem constants
constexpr int B  = 8;
constexpr int S  = 4096;
constexpr int D  = 64;
constexpr int DS = 16;
constexpr int CH = 64;                       // chunk length (tokens)
constexpr int NCHUNKS = B * S / CH;          // 512
constexpr int NTOK = B * S;                  // 32768

constexpr int SXT = 68;                      // sxT row stride (floats), 16B rows
constexpr int SX2 = 65;                      // sx2 (token-major) row stride
constexpr int SHT = 66;                      // shT row stride

// Scratch
__device__ float g_Pref[NTOK * DS * DS];     // 33.5 MB per-token prefix transitions
__device__ float g_r  [NTOK * DS];           //  2  MB per-token prefix offsets
__device__ float g_H0 [NCHUNKS * DS];        // state at each chunk start

// ---------------------------------------------------------------------------
// packed f32x2 helpers (SASS FFMA2 — PTX-only path on sm_103a)
// ---------------------------------------------------------------------------
using u64 = unsigned long long;

__device__ __forceinline__ u64 pack2(float lo, float hi) {
    u64 r; asm("mov.b64 %0, {%1, %2};" : "=l"(r) : "f"(lo), "f"(hi)); return r;
}
__device__ __forceinline__ void unpack2(u64 v, float& lo, float& hi) {
    asm("mov.b64 {%0, %1}, %2;" : "=f"(lo), "=f"(hi) : "l"(v));
}
__device__ __forceinline__ u64 fma2(u64 a, u64 b, u64 c) {
    u64 d; asm("fma.rn.f32x2 %0, %1, %2, %3;" : "=l"(d) : "l"(a), "l"(b), "l"(c)); return d;
}
__device__ __forceinline__ u64 mul2(u64 a, u64 b) {
    u64 d; asm("mul.rn.f32x2 %0, %1, %2;" : "=l"(d) : "l"(a), "l"(b)); return d;
}
__device__ __forceinline__ u64 add2(u64 a, u64 b) {
    u64 d; asm("add.rn.f32x2 %0, %1, %2;" : "=l"(d) : "l"(a), "l"(b)); return d;
}

// cp.async helpers (LDGSTS)
__device__ __forceinline__ uint32_t smem_u32(const void* p) {
    return (uint32_t)__cvta_generic_to_shared(p);
}
__device__ __forceinline__ void cp_async16(uint32_t saddr, const void* gaddr) {
    asm volatile("cp.async.cg.shared.global [%0], [%1], 16;" :: "r"(saddr), "l"(gaddr));
}
__device__ __forceinline__ void cp_commit() {
    asm volatile("cp.async.commit_group;" ::: "memory");
}
template<int N>
__device__ __forceinline__ void cp_wait() {
    asm volatile("cp.async.wait_group %0;" :: "n"(N) : "memory");
}

// transpose-load a 64x64 token-major x chunk into sxT[k*SXT + t]
__device__ __forceinline__ void load_xT(const float* __restrict__ xc, float* sxT, int tid) {
    for (int e = tid; e < 2048; e += 256) {
        const int k  = e & 63;
        const int tp = e >> 6;                 // token pair 0..31
        const float a = xc[(2 * tp)     * 64 + k];
        const float b = xc[(2 * tp + 1) * 64 + k];
        *(float2*)&sxT[k * SXT + 2 * tp] = make_float2(a, b);
    }
}

// ---------------------------------------------------------------------------
// K1: fused per chunk — A projection, Bx (16-token tiles), serial chunk scan
// smem = 105856 B  -> 2 CTAs/SM     (unchanged from best: 188 us)
// ---------------------------------------------------------------------------
__global__ __launch_bounds__(256, 2)
void k1_proj_scan(const float* __restrict__ x,
                  const float* __restrict__ WA, const float* __restrict__ bA,
                  const float* __restrict__ WB, const float* __restrict__ bB)
{
    extern __shared__ float sm[];
    float* sxT = sm;                  // 64*68
    float* sx2 = sxT + 64 * SXT;      // 64*65 token-major
    float* sA  = sx2 + 64 * SX2;      // 64*256
    float* sBx = sA  + 64 * 256;      // 64*16
    float* sP  = sBx + 64 * 16;       // 2*256
    float* sq  = sP  + 512;           // 2*16

    const int c   = blockIdx.x;
    const int tid = threadIdx.x;
    const float* xc = x + (size_t)c * CH * D;

    load_xT(xc, sxT, tid);
    for (int e = tid; e < CH * D; e += 256)
        sx2[(e >> 6) * SX2 + (e & 63)] = xc[e];
    __syncthreads();

    // ---- Phase A
    {
        const int i = tid;
        const float bias = bA[i];
        for (int half = 0; half < 2; ++half) {
            u64 acc[16];
            #pragma unroll
            for (int p = 0; p < 16; ++p) acc[p] = pack2(bias, bias);
            float w0 = WA[0 * 256 + i];
            float w1 = WA[1 * 256 + i];
            #pragma unroll 4
            for (int k = 0; k < 64; ++k) {
                const float w2 = (k < 62) ? WA[(k + 2) * 256 + i] : 0.0f;
                const u64 wp = pack2(w0, w0);
                const float* xrow = &sxT[k * SXT + half * 32];
                #pragma unroll
                for (int q = 0; q < 8; ++q) {
                    const ulonglong2 xv = *(const ulonglong2*)&xrow[q * 4];
                    acc[2 * q]     = fma2(xv.x, wp, acc[2 * q]);
                    acc[2 * q + 1] = fma2(xv.y, wp, acc[2 * q + 1]);
                }
                w0 = w1; w1 = w2;
            }
            #pragma unroll
            for (int p = 0; p < 16; ++p) {
                float lo, hi; unpack2(acc[p], lo, hi);
                const int t0 = half * 32 + 2 * p;
                sA[t0 * 256 + i]       = lo;
                sA[(t0 + 1) * 256 + i] = hi;
            }
        }
    }

    // ---- Phase B (16-token tiles)
    {
        const int n  = tid >> 4;
        const int dq = tid & 15;
        const float4 bb = *(const float4*)&bB[n * 64 + dq * 4];
        const float bbc[4] = {bb.x, bb.y, bb.z, bb.w};
        const float4* WB4 = (const float4*)WB;
        const int widx = n * 16 + dq;

        for (int tt = 0; tt < 4; ++tt) {
            const int base = tt * 16;
            u64 acc[8][4];
            #pragma unroll
            for (int p = 0; p < 8; ++p)
                #pragma unroll
                for (int cc = 0; cc < 4; ++cc) acc[p][cc] = pack2(bbc[cc], bbc[cc]);

            float4 w[4];
            #pragma unroll
            for (int j = 0; j < 4; ++j) w[j] = WB4[j * 256 + widx];
            for (int kg = 0; kg < 16; ++kg) {
                float4 wn[4];
                const int nk = (kg < 15) ? (kg + 1) * 4 : 0;
                #pragma unroll
                for (int j = 0; j < 4; ++j) wn[j] = WB4[(nk + j) * 256 + widx];
                #pragma unroll
                for (int j = 0; j < 4; ++j) {
                    const int k = kg * 4 + j;
                    const u64 wpx = pack2(w[j].x, w[j].x);
                    const u64 wpy = pack2(w[j].y, w[j].y);
                    const u64 wpz = pack2(w[j].z, w[j].z);
                    const u64 wpw = pack2(w[j].w, w[j].w);
                    const float* xr = &sxT[k * SXT + base];
                    const ulonglong2 x0 = *(const ulonglong2*)&xr[0];
                    const ulonglong2 x1 = *(const ulonglong2*)&xr[4];
                    const ulonglong2 x2 = *(const ulonglong2*)&xr[8];
                    const ulonglong2 x3 = *(const ulonglong2*)&xr[12];
                    const u64 xp[8] = {x0.x, x0.y, x1.x, x1.y, x2.x, x2.y, x3.x, x3.y};
                    #pragma unroll
                    for (int p = 0; p < 8; ++p) {
                        acc[p][0] = fma2(xp[p], wpx, acc[p][0]);
                        acc[p][1] = fma2(xp[p], wpy, acc[p][1]);
                        acc[p][2] = fma2(xp[p], wpz, acc[p][2]);
                        acc[p][3] = fma2(xp[p], wpw, acc[p][3]);
                    }
                }
                #pragma unroll
                for (int j = 0; j < 4; ++j) w[j] = wn[j];
            }
            #pragma unroll
            for (int p = 0; p < 8; ++p) {
                const int t0 = base + 2 * p;
                u64 v;
                #pragma unroll
                for (int cc = 0; cc < 4; ++cc) {
                    const int d = dq * 4 + cc;
                    const u64 xpair = pack2(sx2[t0 * SX2 + d], sx2[(t0 + 1) * SX2 + d]);
                    v = (cc == 0) ? mul2(acc[p][0], xpair) : fma2(acc[p][cc], xpair, v);
                }
                v = add2(v, __shfl_xor_sync(0xffffffffu, v, 8, 16));
                v = add2(v, __shfl_xor_sync(0xffffffffu, v, 4, 16));
                v = add2(v, __shfl_xor_sync(0xffffffffu, v, 2, 16));
                v = add2(v, __shfl_xor_sync(0xffffffffu, v, 1, 16));
                if (dq == 0) {
                    float lo, hi; unpack2(v, lo, hi);
                    sBx[t0 * 16 + n]       = lo;
                    sBx[(t0 + 1) * 16 + n] = hi;
                }
            }
        }
    }

    // ---- Phase C: serial chunk scan, emitting every prefix (Pref_t, r_t).
    {
        const int pi = tid >> 4, pj = tid & 15;
        sP[tid] = (pi == pj) ? 1.0f : 0.0f;
        if (tid < 16) sq[tid] = 0.0f;
        __syncthreads();

        float* gP = g_Pref + (size_t)c * CH * 256;
        float* gr = g_r    + (size_t)c * CH * 16;
        int cur = 0;
        for (int t = 0; t < CH; ++t) {
            const float* At = &sA[t * 256];
            float np0 = 0.0f, np1 = 0.0f;
            #pragma unroll
            for (int k = 0; k < 16; k += 2) {
                np0 += At[pi * 16 + k]     * sP[cur * 256 + k * 16 + pj];
                np1 += At[pi * 16 + k + 1] * sP[cur * 256 + (k + 1) * 16 + pj];
            }
            const float np = np0 + np1;
            float nq = 0.0f;
            if (tid < 16) {
                nq = sBx[t * 16 + tid];
                #pragma unroll
                for (int k = 0; k < 16; ++k)
                    nq += At[tid * 16 + k] * sq[cur * 16 + k];
            }
            sP[(cur ^ 1) * 256 + tid] = np;
            if (tid < 16) sq[(cur ^ 1) * 16 + tid] = nq;
            gP[t * 256 + tid] = np;                    // fire-and-forget STG
            if (tid < 16) gr[t * 16 + tid] = nq;
            cur ^= 1;
            __syncthreads();
        }
    }
}

// ---------------------------------------------------------------------------
// K2: per batch — serial scan over 64 chunk-final (P,q) pairs -> g_H0
// ---------------------------------------------------------------------------
__global__ __launch_bounds__(256)
void k2_chain(void)
{
    extern __shared__ float sm[];
    float* cP = sm;            // 64*256
    float* cq = cP + 64 * 256; // 64*16

    const int b   = blockIdx.x;
    const int tid = threadIdx.x;

    for (int e = tid; e < 64 * 256; e += 256) {
        const int cc = e >> 8, el = e & 255;
        cP[e] = g_Pref[((size_t)(b * 64 + cc) * 64 + 63) * 256 + el];
    }
    for (int e = tid; e < 64 * 16; e += 256) {
        const int cc = e >> 4, el = e & 15;
        cq[e] = g_r[((size_t)(b * 64 + cc) * 64 + 63) * 16 + el];
    }
    __syncthreads();

    if (tid < 32) {
        const int lane = tid;
        const int i    = lane & 15;
        const int hb   = (lane >> 4) * 8;
        const int hsel = lane & 16;
        float h = 0.0f;
        for (int cc = 0; cc < 64; ++cc) {
            if (lane < 16) g_H0[(b * 64 + cc) * 16 + i] = h;
            const float4 r0 = *(const float4*)&cP[cc * 256 + i * 16 + hb];
            const float4 r1 = *(const float4*)&cP[cc * 256 + i * 16 + hb + 4];
            float p0, p1;
            p0  = r0.x * __shfl_sync(0xffffffffu, h, hsel | (hb + 0));
            p1  = r0.y * __shfl_sync(0xffffffffu, h, hsel | (hb + 1));
            p0 += r0.z * __shfl_sync(0xffffffffu, h, hsel | (hb + 2));
            p1 += r0.w * __shfl_sync(0xffffffffu, h, hsel | (hb + 3));
            p0 += r1.x * __shfl_sync(0xffffffffu, h, hsel | (hb + 4));
            p1 += r1.y * __shfl_sync(0xffffffffu, h, hsel | (hb + 5));
            p0 += r1.z * __shfl_sync(0xffffffffu, h, hsel | (hb + 6));
            p1 += r1.w * __shfl_sync(0xffffffffu, h, hsel | (hb + 7));
            float part = p0 + p1;
            part += __shfl_xor_sync(0xffffffffu, part, 16);
            h = cq[cc * 16 + i] + part;
        }
    }
}

// ---------------------------------------------------------------------------
// K3: per chunk — h_t = Pref_t @ h0 + r_t (parallel), then
//     out = (x@W_C + b_C)^T h with W_C staged per-n in smem (cp.async,
//     double-buffered).  smem = 17408+4224+64+32768 = 54464 B.
// ---------------------------------------------------------------------------
__global__ __launch_bounds__(256, 2)
void k3_out(const float* __restrict__ x,
            const float* __restrict__ WC, const float* __restrict__ bC,
            float* __restrict__ out)
{
    __shared__ float sxT[64 * SXT];
    __shared__ float shT[16 * SHT];   // shT[n*SHT + t]
    __shared__ float sh0[16];
    __shared__ float sW[2][64 * 64];  // per-n W_C slice, double-buffered

    const int c   = blockIdx.x;
    const int tid = threadIdx.x;
    const float* xc = x + (size_t)c * CH * D;

    load_xT(xc, sxT, tid);
    if (tid < 16) sh0[tid] = g_H0[c * 16 + tid];
    __syncthreads();

    // h for every token, fully parallel; stored transposed shT[n][t]
    {
        const float* gP = g_Pref + (size_t)c * CH * 256;
        const float* gr = g_r    + (size_t)c * CH * 16;
        #pragma unroll
        for (int u = 0; u < 4; ++u) {
            const int e = tid + 256 * u;   // 0..1023
            const int t = e >> 4, n = e & 15;
            const float4* prow = (const float4*)(gP + t * 256 + n * 16);
            float acc = gr[e];
            #pragma unroll
            for (int jq = 0; jq < 4; ++jq) {
                const float4 p  = prow[jq];
                const float4 h0 = *(const float4*)&sh0[jq * 4];
                acc += p.x * h0.x + p.y * h0.y + p.z * h0.z + p.w * h0.w;
            }
            shT[n * SHT + t] = acc;
        }
    }

    // stage W_C n-slice loader: 16 KB = 1024 float4; thread does 4 x 16B
    auto stage = [&](int n, int buf) {
        const float4* src = (const float4*)WC;   // [k*256 + n*16 + c4]
        #pragma unroll
        for (int it = 0; it < 4; ++it) {
            const int idx = tid + 256 * it;       // float4 index 0..1023
            const int k   = idx >> 4;
            const int c4  = idx & 15;
            cp_async16(smem_u32(&sW[buf][idx * 4]), &src[k * 256 + n * 16 + c4]);
        }
        cp_commit();
    };

    stage(0, 0);

    const int dq = tid & 15;
    const int tg = tid >> 4;
    const int tb = tg * 4;
    u64 oacc[2][4];
    #pragma unroll
    for (int p = 0; p < 2; ++p)
        #pragma unroll
        for (int cc = 0; cc < 4; ++cc) oacc[p][cc] = 0ull;

    for (int n = 0; n < 16; ++n) {
        cp_wait<0>();
        __syncthreads();                          // sW[n&1] ready; prev buf free
        if (n < 15) stage(n + 1, (n + 1) & 1);

        const float* wb = sW[n & 1];              // [k*64 + d]
        const float4 bcn = *(const float4*)&bC[n * 64 + dq * 4];
        const float bcc[4] = {bcn.x, bcn.y, bcn.z, bcn.w};
        u64 cm[2][4];
        #pragma unroll
        for (int p = 0; p < 2; ++p)
            #pragma unroll
            for (int cc = 0; cc < 4; ++cc) cm[p][cc] = pack2(bcc[cc], bcc[cc]);

        #pragma unroll 4
        for (int k = 0; k < 64; ++k) {
            const float4 w = *(const float4*)&wb[k * 64 + dq * 4];
            const u64 wpx = pack2(w.x, w.x);
            const u64 wpy = pack2(w.y, w.y);
            const u64 wpz = pack2(w.z, w.z);
            const u64 wpw = pack2(w.w, w.w);
            const ulonglong2 xa = *(const ulonglong2*)&sxT[k * SXT + tb];
            cm[0][0] = fma2(xa.x, wpx, cm[0][0]);
            cm[0][1] = fma2(xa.x, wpy, cm[0][1]);
            cm[0][2] = fma2(xa.x, wpz, cm[0][2]);
            cm[0][3] = fma2(xa.x, wpw, cm[0][3]);
            cm[1][0] = fma2(xa.y, wpx, cm[1][0]);
            cm[1][1] = fma2(xa.y, wpy, cm[1][1]);
            cm[1][2] = fma2(xa.y, wpz, cm[1][2]);
            cm[1][3] = fma2(xa.y, wpw, cm[1][3]);
        }
        // fold with h_n for this token pair
        #pragma unroll
        for (int p = 0; p < 2; ++p) {
            const u64 hp = *(const u64*)&shT[n * SHT + tb + 2 * p];
            #pragma unroll
            for (int cc = 0; cc < 4; ++cc)
                oacc[p][cc] = fma2(hp, cm[p][cc], oacc[p][cc]);
        }
    }

    // store: unpack token pairs into float4 rows
    #pragma unroll
    for (int p = 0; p < 2; ++p) {
        float4 o0, o1;
        unpack2(oacc[p][0], o0.x, o1.x);
        unpack2(oacc[p][1], o0.y, o1.y);
        unpack2(oacc[p][2], o0.z, o1.z);
        unpack2(oacc[p][3], o0.w, o1.w);
        const int t0 = tb + 2 * p;
        *(float4*)&out[((size_t)c * CH + t0)     * 64 + dq * 4] = o0;
        *(float4*)&out[((size_t)c * CH + t0 + 1) * 64 + dq * 4] = o1;
    }
}

// ---------------------------------------------------------------------------
extern "C" void kernel_launch(void* const* d_in, const int* in_sizes, int n_in,
                              void* d_out, int out_size)
{
    const float* x  = (const float*)d_in[0];
    const float* WA = (const float*)d_in[1];
    const float* bA = (const float*)d_in[2];
    const float* WB = (const float*)d_in[3];
    const float* bB = (const float*)d_in[4];
    const float* WC = (const float*)d_in[5];
    const float* bC = (const float*)d_in[6];
    float* out = (float*)d_out;

    const int smem1 = (64 * SXT + 64 * SX2 + 64 * 256 + 64 * 16 + 512 + 32) * 4; // 105856
    const int smem2 = (64 * 256 + 64 * 16) * 4;                                  // 69632

    cudaFuncSetAttribute(k1_proj_scan, cudaFuncAttributeMaxDynamicSharedMemorySize, smem1);
    cudaFuncSetAttribute(k2_chain,     cudaFuncAttributeMaxDynamicSharedMemorySize, smem2);

    k1_proj_scan<<<NCHUNKS, 256, smem1>>>(x, WA, bA, WB, bB);
    k2_chain    <<<B,       256, smem2>>>();
    k3_out      <<<NCHUNKS, 256>>>(x, WC, bC, out);
}